// round 2
// baseline (speedup 1.0000x reference)
#include <cuda_runtime.h>
#include <cuda_bf16.h>
#include <cstdint>

// Problem constants
#define H_IMG 64
#define W_IMG 64
#define C_IMG 3
#define PAD 10
#define KH 32
#define KW 32
#define LH 53                  // H + 2*PAD - KH + 1
#define LW 53
#define M_PATCH 2809           // LH*LW
#define M_PAD 2816             // padded to multiple of 128
#define N_MEM 8192
#define K_DIM 3072             // C*KH*KW

// ---------------- device scratch (static, allocation-free) ----------------
__device__ float g_patches[(size_t)M_PAD * K_DIM];   // 34.6 MB
__device__ float g_mem_sq[N_MEM];
__device__ unsigned long long g_min[M_PAD];          // (key<<32)|index
__device__ int g_row[M_PAD];                         // mapping[nn[p]]
__device__ unsigned int g_max_key;

// order-preserving float <-> uint key
__device__ __forceinline__ unsigned int fkey(float f) {
    unsigned int u = __float_as_uint(f);
    return (u & 0x80000000u) ? ~u : (u | 0x80000000u);
}
__device__ __forceinline__ float fdecode(unsigned int k) {
    unsigned int u = (k & 0x80000000u) ? (k & 0x7FFFFFFFu) : ~k;
    return __uint_as_float(u);
}

// ---------------- kernels ----------------

__global__ void k_init() {
    int i = blockIdx.x * blockDim.x + threadIdx.x;
    if (i < M_PAD) g_min[i] = 0xFFFFFFFFFFFFFFFFull;
    if (i == 0) g_max_key = 0u;
}

// build patches matrix: g_patches[p][k], p=(i,j) window, k=(c,ki,kj)
// grid: M_PAD * (K_DIM/256) blocks of 256
__global__ void k_build(const float* __restrict__ image) {
    int p = blockIdx.x / 12;                   // K_DIM/256 = 12
    int k = (blockIdx.x % 12) * 256 + threadIdx.x;
    if (p >= M_PAD) return;
    float val = 0.0f;
    if (p < M_PATCH) {
        int i = p / LW;
        int j = p - i * LW;
        int c = k >> 10;
        int r = k & 1023;
        int ki = r >> 5;
        int kj = r & 31;
        int y = i + ki - PAD;
        int x = j + kj - PAD;
        if ((unsigned)y < H_IMG && (unsigned)x < W_IMG)
            val = image[(y * W_IMG + x) * C_IMG + c];
    }
    g_patches[(size_t)p * K_DIM + k] = val;
}

// mem_sq[n] = sum_k mem[n][k]^2 ; one warp per row
__global__ void k_memsq(const float* __restrict__ mem) {
    int row = blockIdx.x * 8 + (threadIdx.x >> 5);
    int lane = threadIdx.x & 31;
    if (row >= N_MEM) return;
    const float4* r = (const float4*)(mem + (size_t)row * K_DIM);
    float s = 0.0f;
    #pragma unroll 4
    for (int q = lane; q < K_DIM / 4; q += 32) {
        float4 v = r[q];
        s += v.x * v.x + v.y * v.y + v.z * v.z + v.w * v.w;
    }
    #pragma unroll
    for (int o = 16; o; o >>= 1) s += __shfl_xor_sync(0xFFFFFFFFu, s, o);
    if (lane == 0) g_mem_sq[row] = s;
}

// Fused GEMM + argmin.  C-tile 128x128, BK=16, 256 threads, 8x8 per thread.
// A = g_patches (MxK), B = mem (NxK), dist = mem_sq[n] - 2*dot
__global__ __launch_bounds__(256) void k_gemm_argmin(const float* __restrict__ mem) {
    const int tid = threadIdx.x;
    const int tx = tid & 15;
    const int ty = tid >> 4;
    const int m0 = blockIdx.y * 128;
    const int n0 = blockIdx.x * 128;

    __shared__ float As[16][132];
    __shared__ float Bs[16][132];

    float acc[8][8];
    #pragma unroll
    for (int i = 0; i < 8; i++)
        #pragma unroll
        for (int j = 0; j < 8; j++) acc[i][j] = 0.0f;

    // load slots: slot s -> row = s>>2 (m or n within tile), kq = s&3 (float4 within BK)
    const int mA0 = (tid) >> 2,        kqA0 = tid & 3;
    const int mA1 = (tid + 256) >> 2,  kqA1 = (tid + 256) & 3;

    const float* pa0 = g_patches + (size_t)(m0 + mA0) * K_DIM + kqA0 * 4;
    const float* pa1 = g_patches + (size_t)(m0 + mA1) * K_DIM + kqA1 * 4;
    const float* pb0 = mem + (size_t)(n0 + mA0) * K_DIM + kqA0 * 4;
    const float* pb1 = mem + (size_t)(n0 + mA1) * K_DIM + kqA1 * 4;

    float4 ra0 = *(const float4*)(pa0);
    float4 ra1 = *(const float4*)(pa1);
    float4 rb0 = *(const float4*)(pb0);
    float4 rb1 = *(const float4*)(pb1);

    for (int kt = 0; kt < K_DIM; kt += 16) {
        // store prefetched tile to smem (transposed)
        As[kqA0 * 4 + 0][mA0] = ra0.x; As[kqA0 * 4 + 1][mA0] = ra0.y;
        As[kqA0 * 4 + 2][mA0] = ra0.z; As[kqA0 * 4 + 3][mA0] = ra0.w;
        As[kqA1 * 4 + 0][mA1] = ra1.x; As[kqA1 * 4 + 1][mA1] = ra1.y;
        As[kqA1 * 4 + 2][mA1] = ra1.z; As[kqA1 * 4 + 3][mA1] = ra1.w;
        Bs[kqA0 * 4 + 0][mA0] = rb0.x; Bs[kqA0 * 4 + 1][mA0] = rb0.y;
        Bs[kqA0 * 4 + 2][mA0] = rb0.z; Bs[kqA0 * 4 + 3][mA0] = rb0.w;
        Bs[kqA1 * 4 + 0][mA1] = rb1.x; Bs[kqA1 * 4 + 1][mA1] = rb1.y;
        Bs[kqA1 * 4 + 2][mA1] = rb1.z; Bs[kqA1 * 4 + 3][mA1] = rb1.w;
        __syncthreads();

        int ktn = kt + 16;
        if (ktn < K_DIM) {  // prefetch next tile (overlaps with compute)
            ra0 = *(const float4*)(pa0 + ktn);
            ra1 = *(const float4*)(pa1 + ktn);
            rb0 = *(const float4*)(pb0 + ktn);
            rb1 = *(const float4*)(pb1 + ktn);
        }

        #pragma unroll
        for (int kk = 0; kk < 16; kk++) {
            float4 a0 = *(const float4*)&As[kk][ty * 8];
            float4 a1 = *(const float4*)&As[kk][ty * 8 + 4];
            float4 b0 = *(const float4*)&Bs[kk][tx * 8];
            float4 b1 = *(const float4*)&Bs[kk][tx * 8 + 4];
            float ra[8] = {a0.x, a0.y, a0.z, a0.w, a1.x, a1.y, a1.z, a1.w};
            float rb[8] = {b0.x, b0.y, b0.z, b0.w, b1.x, b1.y, b1.z, b1.w};
            #pragma unroll
            for (int i = 0; i < 8; i++)
                #pragma unroll
                for (int j = 0; j < 8; j++)
                    acc[i][j] += ra[i] * rb[j];
        }
        __syncthreads();
    }

    // epilogue: dist = mem_sq - 2*score, argmin over this CTA's 128 n values
    float msq[8];
    #pragma unroll
    for (int j = 0; j < 8; j++) msq[j] = g_mem_sq[n0 + tx * 8 + j];

    #pragma unroll
    for (int i = 0; i < 8; i++) {
        int m = m0 + ty * 8 + i;
        unsigned long long best = 0xFFFFFFFFFFFFFFFFull;
        #pragma unroll
        for (int j = 0; j < 8; j++) {
            float d = msq[j] - 2.0f * acc[i][j];
            unsigned long long c =
                ((unsigned long long)fkey(d) << 32) | (unsigned)(n0 + tx * 8 + j);
            best = (c < best) ? c : best;
        }
        // reduce across the 16 tx lanes (xor 8,4,2,1 stays inside the 16-group)
        #pragma unroll
        for (int o = 8; o; o >>= 1) {
            unsigned long long other = __shfl_xor_sync(0xFFFFFFFFu, best, o);
            best = (other < best) ? other : best;
        }
        if (tx == 0 && m < M_PATCH) atomicMin(&g_min[m], best);
    }
}

__global__ void k_rowmap(const int* __restrict__ mapping) {
    int p = blockIdx.x * blockDim.x + threadIdx.x;
    if (p < M_PATCH) {
        unsigned nn = (unsigned)(g_min[p] & 0xFFFFFFFFull);
        g_row[p] = mapping[nn];
    }
}

// one block per output pixel: gather overlap-add contributions (atomic-free)
__global__ void k_output(const float* __restrict__ mem2, float* __restrict__ out) {
    int pix = blockIdx.x;             // = (y*64 + x)*3 + c  (output layout H,W,C)
    int y = pix / (W_IMG * C_IMG);
    int rem = pix - y * (W_IMG * C_IMG);
    int x = rem / C_IMG;
    int c = rem - x * C_IMG;

    float s = 0.0f;
    for (int idx = threadIdx.x; idx < KH * KW; idx += 256) {
        int ki = idx >> 5;
        int kj = idx & 31;
        int i = y + PAD - ki;
        int j = x + PAD - kj;
        if ((unsigned)i < LH && (unsigned)j < LW) {
            int row = g_row[i * LW + j];
            s += mem2[(size_t)row * K_DIM + c * (KH * KW) + idx];
        }
    }
    #pragma unroll
    for (int o = 16; o; o >>= 1) s += __shfl_xor_sync(0xFFFFFFFFu, s, o);
    __shared__ float red[8];
    if ((threadIdx.x & 31) == 0) red[threadIdx.x >> 5] = s;
    __syncthreads();
    if (threadIdx.x == 0) {
        float t = red[0];
        #pragma unroll
        for (int w = 1; w < 8; w++) t += red[w];
        out[pix] = t;
        atomicMax(&g_max_key, fkey(t));
    }
}

__global__ void k_norm(float* __restrict__ out) {
    int i = blockIdx.x * blockDim.x + threadIdx.x;
    if (i < H_IMG * W_IMG * C_IMG) out[i] /= fdecode(g_max_key);
}

// ---------------- launch ----------------
extern "C" void kernel_launch(void* const* d_in, const int* in_sizes, int n_in,
                              void* d_out, int out_size) {
    const float* image   = (const float*)d_in[0];
    const float* mem     = (const float*)d_in[1];
    const float* mem2    = (const float*)d_in[2];
    const int*   mapping = (const int*)d_in[3];
    float* out = (float*)d_out;

    k_init<<<(M_PAD + 255) / 256, 256>>>();
    k_build<<<M_PAD * (K_DIM / 256), 256>>>(image);
    k_memsq<<<N_MEM / 8, 256>>>(mem);
    dim3 gemm_grid(N_MEM / 128, M_PAD / 128);
    k_gemm_argmin<<<gemm_grid, 256>>>(mem);
    k_rowmap<<<(M_PATCH + 255) / 256, 256>>>(mapping);
    k_output<<<H_IMG * W_IMG * C_IMG, 256>>>(mem2, out);
    k_norm<<<(H_IMG * W_IMG * C_IMG + 255) / 256, 256>>>(out);
}

// round 4
// speedup vs baseline: 7.3839x; 7.3839x over previous
#include <cuda_runtime.h>
#include <cuda_bf16.h>
#include <cstdint>

// Problem constants
#define H_IMG 64
#define W_IMG 64
#define C_IMG 3
#define PAD 10
#define KH 32
#define KW 32
#define LH 53
#define LW 53
#define M_PATCH 2809
#define M_PAD 2816
#define N_MEM 8192
#define K_DIM 3072

// GEMM tiling
#define BM 128
#define BN 256
#define BK 64
#define NKB (K_DIM / BK)                  // 48
#define STAGE_BYTES (BM * 128 + BN * 128) // 49152
#define SMEM_DYN (1024 + 2 * STAGE_BYTES)

typedef unsigned long long ull;

// ---------------- device scratch ----------------
__device__ __align__(128) float          g_patches[(size_t)M_PAD * K_DIM];
__device__ __align__(128) __nv_bfloat16  g_patch_bf16[(size_t)M_PAD * K_DIM];
__device__ __align__(128) __nv_bfloat16  g_mem_bf16[(size_t)N_MEM * K_DIM];
__device__ float g_mem_sq[N_MEM];
__device__ ull g_top2[(size_t)M_PAD * 64];   // top-2 per (m, 256-col chunk)
__device__ int g_row[M_PAD];
__device__ unsigned int g_max_key;

__device__ __forceinline__ unsigned int fkey(float f) {
    unsigned int u = __float_as_uint(f);
    return (u & 0x80000000u) ? ~u : (u | 0x80000000u);
}
__device__ __forceinline__ float fdecode(unsigned int k) {
    unsigned int u = (k & 0x80000000u) ? (k & 0x7FFFFFFFu) : ~k;
    return __uint_as_float(u);
}

// ---------------- PTX helpers (sm_80-compatible only) ----------------
__device__ __forceinline__ uint32_t smem_u32(const void* p) {
    uint32_t a;
    asm("{ .reg .u64 t; cvta.to.shared.u64 t, %1; cvt.u32.u64 %0, t; }" : "=r"(a) : "l"(p));
    return a;
}
#define CP_ASYNC16(s, g) \
    asm volatile("cp.async.cg.shared.global [%0], [%1], 16;" :: "r"(s), "l"(g))
#define CP_COMMIT() asm volatile("cp.async.commit_group;" ::: "memory")
#define CP_WAIT1()  asm volatile("cp.async.wait_group 1;" ::: "memory")
#define CP_WAIT0()  asm volatile("cp.async.wait_group 0;" ::: "memory")

#define LDSM_X4(r, a)                                                            \
    asm volatile("ldmatrix.sync.aligned.m8n8.x4.shared.b16 {%0,%1,%2,%3}, [%4];" \
                 : "=r"((r)[0]), "=r"((r)[1]), "=r"((r)[2]), "=r"((r)[3]) : "r"(a))

__device__ __forceinline__ void mma_bf16(float* c, const uint32_t* a,
                                         uint32_t b0, uint32_t b1) {
    asm volatile(
        "mma.sync.aligned.m16n8k16.row.col.f32.bf16.bf16.f32 "
        "{%0,%1,%2,%3}, {%4,%5,%6,%7}, {%8,%9}, {%0,%1,%2,%3};"
        : "+f"(c[0]), "+f"(c[1]), "+f"(c[2]), "+f"(c[3])
        : "r"(a[0]), "r"(a[1]), "r"(a[2]), "r"(a[3]), "r"(b0), "r"(b1));
}

__device__ __forceinline__ uint32_t sw128(uint32_t off) {
    return off ^ ((off >> 3) & 0x70);
}
__device__ __forceinline__ void top2_merge(ull& x0, ull& x1, ull y0, ull y1) {
    ull n0 = x0 < y0 ? x0 : y0;
    ull hi = x0 < y0 ? y0 : x0;
    ull lo1 = x1 < y1 ? x1 : y1;
    x1 = hi < lo1 ? hi : lo1;
    x0 = n0;
}

// ---------------- small kernels ----------------
__global__ void k_init0() {
    if (threadIdx.x == 0 && blockIdx.x == 0) g_max_key = 0u;
}

__global__ void k_build(const float* __restrict__ image) {
    int idx = blockIdx.x * 256 + threadIdx.x;
    int p = idx / 1536;
    int kp = idx - p * 1536;
    int k0 = kp * 2;
    if (p >= M_PAD) return;
    float v0 = 0.0f, v1 = 0.0f;
    if (p < M_PATCH) {
        int i = p / LW;
        int j = p - i * LW;
        #pragma unroll
        for (int t = 0; t < 2; t++) {
            int k = k0 + t;
            int c = k >> 10;
            int r = k & 1023;
            int ki = r >> 5;
            int kj = r & 31;
            int y = i + ki - PAD;
            int x = j + kj - PAD;
            float v = 0.0f;
            if ((unsigned)y < H_IMG && (unsigned)x < W_IMG)
                v = image[(y * W_IMG + x) * C_IMG + c];
            if (t == 0) v0 = v; else v1 = v;
        }
    }
    size_t o = (size_t)p * K_DIM + k0;
    g_patches[o] = v0;
    g_patches[o + 1] = v1;
    *(__nv_bfloat162*)(g_patch_bf16 + o) = __floats2bfloat162_rn(v0, v1);
}

__global__ void k_convert(const float* __restrict__ mem) {
    size_t idx = (size_t)blockIdx.x * 256 + threadIdx.x;
    if (idx >= (size_t)N_MEM * K_DIM / 4) return;
    float4 v = ((const float4*)mem)[idx];
    __nv_bfloat162* o = (__nv_bfloat162*)(g_mem_bf16 + idx * 4);
    o[0] = __floats2bfloat162_rn(v.x, v.y);
    o[1] = __floats2bfloat162_rn(v.z, v.w);
}

__global__ void k_memsq(const float* __restrict__ mem) {
    int row = blockIdx.x * 8 + (threadIdx.x >> 5);
    int lane = threadIdx.x & 31;
    if (row >= N_MEM) return;
    const float4* r = (const float4*)(mem + (size_t)row * K_DIM);
    float s = 0.0f;
    #pragma unroll 4
    for (int q = lane; q < K_DIM / 4; q += 32) {
        float4 v = r[q];
        s += v.x * v.x + v.y * v.y + v.z * v.z + v.w * v.w;
    }
    #pragma unroll
    for (int o = 16; o; o >>= 1) s += __shfl_xor_sync(0xFFFFFFFFu, s, o);
    if (lane == 0) g_mem_sq[row] = s;
}

// ---------------- bf16 mma.sync GEMM + top-2 epilogue ----------------
// grid (N/256, M/128), 256 threads (8 warps, 2m x 4n, warp tile 64x64)
__global__ __launch_bounds__(256) void k_gemm_mma() {
    extern __shared__ char dsm[];
    __shared__ float s_msq[256];
    __shared__ ull s_red[128][4][2];

    const int tid = threadIdx.x;
    const int wid = tid >> 5;
    const int lane = tid & 31;
    const int wm = wid >> 2;          // 0..1
    const int wn = wid & 3;           // 0..3
    const int m0 = blockIdx.y * BM;
    const int n0 = blockIdx.x * BN;

    uint32_t sbase = (smem_u32(dsm) + 1023u) & ~1023u;
    uint32_t sA[2], sB[2];
    #pragma unroll
    for (int s = 0; s < 2; s++) {
        sA[s] = sbase + s * STAGE_BYTES;
        sB[s] = sA[s] + BM * 128;
    }

    s_msq[tid] = g_mem_sq[n0 + tid];

    const __nv_bfloat16* Abase = g_patch_bf16 + (size_t)m0 * K_DIM;
    const __nv_bfloat16* Bbase = g_mem_bf16 + (size_t)n0 * K_DIM;

    auto load_stage = [&](int stg, int kb) {
        const __nv_bfloat16* Ab = Abase + kb * BK;
        const __nv_bfloat16* Bb = Bbase + kb * BK;
        #pragma unroll
        for (int r = 0; r < 4; r++) {
            int c = tid + r * 256;
            int row = c >> 3, kc = c & 7;
            CP_ASYNC16(sA[stg] + sw128((uint32_t)(row * 128 + kc * 16)),
                       Ab + (size_t)row * K_DIM + kc * 8);
        }
        #pragma unroll
        for (int r = 0; r < 8; r++) {
            int c = tid + r * 256;
            int row = c >> 3, kc = c & 7;
            CP_ASYNC16(sB[stg] + sw128((uint32_t)(row * 128 + kc * 16)),
                       Bb + (size_t)row * K_DIM + kc * 8);
        }
    };

    float acc[4][8][4];
    #pragma unroll
    for (int mi = 0; mi < 4; mi++)
        #pragma unroll
        for (int ni = 0; ni < 8; ni++)
            #pragma unroll
            for (int q = 0; q < 4; q++) acc[mi][ni][q] = 0.0f;

    load_stage(0, 0);
    CP_COMMIT();

    // precomputed per-lane ldmatrix offsets (within tile, before kk shift)
    const uint32_t a_row = (uint32_t)(wm * 64 + (lane & 15));
    const uint32_t a_kg = (uint32_t)((lane >> 4) * 16);
    const uint32_t b_row = (uint32_t)(wn * 64 + (lane & 7) + ((lane >> 4) & 1) * 8);
    const uint32_t b_kg = (uint32_t)(((lane >> 3) & 1) * 16);

    for (int kb = 0; kb < NKB; kb++) {
        int buf = kb & 1;
        if (kb + 1 < NKB) {
            load_stage(buf ^ 1, kb + 1);
            CP_COMMIT();
            CP_WAIT1();
        } else {
            CP_WAIT0();
        }
        __syncthreads();

        #pragma unroll
        for (int kk = 0; kk < 4; kk++) {
            uint32_t af[4][4];
            #pragma unroll
            for (int mi = 0; mi < 4; mi++) {
                uint32_t off = (a_row + mi * 16) * 128 + kk * 32 + a_kg;
                LDSM_X4(af[mi], sA[buf] + sw128(off));
            }
            uint32_t bf[4][4];
            #pragma unroll
            for (int nt = 0; nt < 4; nt++) {
                uint32_t off = (b_row + nt * 16) * 128 + kk * 32 + b_kg;
                LDSM_X4(bf[nt], sB[buf] + sw128(off));
            }
            #pragma unroll
            for (int mi = 0; mi < 4; mi++)
                #pragma unroll
                for (int ni = 0; ni < 8; ni++) {
                    const uint32_t* bt = bf[ni >> 1];
                    if (ni & 1) mma_bf16(acc[mi][ni], af[mi], bt[2], bt[3]);
                    else        mma_bf16(acc[mi][ni], af[mi], bt[0], bt[1]);
                }
        }
        __syncthreads();
    }

    // ---- epilogue: dist = msq - 2*score, per-row top-2 over this 256-chunk ----
    const int qrow = lane >> 2;
    const int qcol = lane & 3;
    #pragma unroll
    for (int mi = 0; mi < 4; mi++) {
        #pragma unroll
        for (int rh = 0; rh < 2; rh++) {
            int row_local = wm * 64 + mi * 16 + qrow + rh * 8;
            ull b0 = 0xFFFFFFFFFFFFFFFFull, b1 = 0xFFFFFFFFFFFFFFFFull;
            #pragma unroll
            for (int ni = 0; ni < 8; ni++) {
                int nc = wn * 64 + ni * 8 + qcol * 2;
                float d0 = s_msq[nc] - 2.0f * acc[mi][ni][rh * 2 + 0];
                float d1 = s_msq[nc + 1] - 2.0f * acc[mi][ni][rh * 2 + 1];
                ull k0 = ((ull)fkey(d0) << 32) | (unsigned)(n0 + nc);
                ull k1 = ((ull)fkey(d1) << 32) | (unsigned)(n0 + nc + 1);
                if (k0 < b0) { b1 = b0; b0 = k0; } else if (k0 < b1) b1 = k0;
                if (k1 < b0) { b1 = b0; b0 = k1; } else if (k1 < b1) b1 = k1;
            }
            #pragma unroll
            for (int o = 1; o <= 2; o <<= 1) {
                ull y0 = __shfl_xor_sync(0xFFFFFFFFu, b0, o);
                ull y1 = __shfl_xor_sync(0xFFFFFFFFu, b1, o);
                top2_merge(b0, b1, y0, y1);
            }
            if (qcol == 0) {
                s_red[row_local][wn][0] = b0;
                s_red[row_local][wn][1] = b1;
            }
        }
    }
    __syncthreads();
    if (tid < 128) {
        ull b0 = 0xFFFFFFFFFFFFFFFFull, b1 = 0xFFFFFFFFFFFFFFFFull;
        #pragma unroll
        for (int w = 0; w < 4; w++)
            top2_merge(b0, b1, s_red[tid][w][0], s_red[tid][w][1]);
        size_t o = (size_t)(m0 + tid) * 64 + blockIdx.x * 2;
        g_top2[o] = b0;
        g_top2[o + 1] = b1;
    }
}

// ---------------- candidate select + exact fp32 rescore ----------------
__global__ void k_select(const float* __restrict__ mem, const int* __restrict__ mapping) {
    int p = blockIdx.x;
    int tid = threadIdx.x;  // 128
    __shared__ ull s_ent[64];
    __shared__ int s_cand[16];
    __shared__ int s_cnt;
    __shared__ float s_part[4];
    __shared__ ull s_best;

    if (tid < 64) s_ent[tid] = g_top2[(size_t)p * 64 + tid];
    __syncthreads();
    if (tid == 0) {
        ull mk = s_ent[0];
        for (int i = 1; i < 64; i++) if (s_ent[i] < mk) mk = s_ent[i];
        float thr = fdecode((unsigned)(mk >> 32)) + 3.0f;
        int c = 0;
        for (int i = 0; i < 64; i++) {
            float f = fdecode((unsigned)(s_ent[i] >> 32));
            if (f < thr && c < 16) s_cand[c++] = (int)(s_ent[i] & 0xFFFFFFFFull);
        }
        s_cnt = c;
        s_best = 0xFFFFFFFFFFFFFFFFull;
    }
    __syncthreads();

    int cnt = s_cnt;
    const float4* prow = (const float4*)(g_patches + (size_t)p * K_DIM);
    for (int ci = 0; ci < cnt; ci++) {
        int n = s_cand[ci];
        const float4* mrow = (const float4*)(mem + (size_t)n * K_DIM);
        float acc = 0.0f;
        for (int q = tid; q < K_DIM / 4; q += 128) {
            float4 a = prow[q];
            float4 b = mrow[q];
            acc += a.x * b.x + a.y * b.y + a.z * b.z + a.w * b.w;
        }
        #pragma unroll
        for (int o = 16; o; o >>= 1) acc += __shfl_xor_sync(0xFFFFFFFFu, acc, o);
        if ((tid & 31) == 0) s_part[tid >> 5] = acc;
        __syncthreads();
        if (tid == 0) {
            float dot = s_part[0] + s_part[1] + s_part[2] + s_part[3];
            float dist = g_mem_sq[n] - 2.0f * dot;
            ull key = ((ull)fkey(dist) << 32) | (unsigned)n;
            if (key < s_best) s_best = key;
        }
        __syncthreads();
    }
    if (tid == 0) g_row[p] = mapping[(int)(s_best & 0xFFFFFFFFull)];
}

// ---------------- output gather + normalize ----------------
__global__ void k_output(const float* __restrict__ mem2, float* __restrict__ out) {
    int pix = blockIdx.x;
    int y = pix / (W_IMG * C_IMG);
    int rem = pix - y * (W_IMG * C_IMG);
    int x = rem / C_IMG;
    int c = rem - x * C_IMG;

    float s = 0.0f;
    for (int idx = threadIdx.x; idx < KH * KW; idx += 256) {
        int ki = idx >> 5;
        int kj = idx & 31;
        int i = y + PAD - ki;
        int j = x + PAD - kj;
        if ((unsigned)i < LH && (unsigned)j < LW) {
            int row = g_row[i * LW + j];
            s += mem2[(size_t)row * K_DIM + c * (KH * KW) + idx];
        }
    }
    #pragma unroll
    for (int o = 16; o; o >>= 1) s += __shfl_xor_sync(0xFFFFFFFFu, s, o);
    __shared__ float red[8];
    if ((threadIdx.x & 31) == 0) red[threadIdx.x >> 5] = s;
    __syncthreads();
    if (threadIdx.x == 0) {
        float t = red[0];
        #pragma unroll
        for (int w = 1; w < 8; w++) t += red[w];
        out[pix] = t;
        atomicMax(&g_max_key, fkey(t));
    }
}

__global__ void k_norm(float* __restrict__ out) {
    int i = blockIdx.x * blockDim.x + threadIdx.x;
    if (i < H_IMG * W_IMG * C_IMG) out[i] /= fdecode(g_max_key);
}

// ---------------- launch ----------------
extern "C" void kernel_launch(void* const* d_in, const int* in_sizes, int n_in,
                              void* d_out, int out_size) {
    const float* image   = (const float*)d_in[0];
    const float* mem     = (const float*)d_in[1];
    const float* mem2    = (const float*)d_in[2];
    const int*   mapping = (const int*)d_in[3];
    float* out = (float*)d_out;

    cudaFuncSetAttribute(k_gemm_mma, cudaFuncAttributeMaxDynamicSharedMemorySize, SMEM_DYN);

    k_init0<<<1, 32>>>();
    k_build<<<(M_PAD * 1536) / 256, 256>>>(image);
    k_convert<<<(int)(((size_t)N_MEM * K_DIM / 4 + 255) / 256), 256>>>(mem);
    k_memsq<<<N_MEM / 8, 256>>>(mem);
    dim3 gg(N_MEM / BN, M_PAD / BM);
    k_gemm_mma<<<gg, 256, SMEM_DYN>>>();
    k_select<<<M_PATCH, 128>>>(mem, mapping);
    k_output<<<H_IMG * W_IMG * C_IMG, 256>>>(mem2, out);
    k_norm<<<(H_IMG * W_IMG * C_IMG + 255) / 256, 256>>>(out);
}